// round 16
// baseline (speedup 1.0000x reference)
#include <cuda_runtime.h>
#include <cuda_fp16.h>
#include <math.h>
#include <stdint.h>

#define NN 50000
#define EE 850000
#define FD 256      // HEADS*HID
#define HEADS 4
#define CH 64
#define OUTD 40
#define K2 128      // K/2 pairs (all GEMMs have K=256)
#define HALF_N 25088  // 196 * 128
#define BN_EPS 1e-5f
#define NEG_SLOPE 0.2f

// ---------------- scratch (static, allocation-free) ----------------
__device__ __align__(256) __half   g_h16[NN * FD];   // GEMM out (fp16) for aggregation
__device__ __align__(256) __half   g_x16[NN * FD];   // activations (fp16 A; layer0 input + inter-layer)
__device__ __align__(256) uint32_t g_w0h[256 * K2], g_w0l[256 * K2];   // fp16 planes
__device__ __align__(256) uint32_t g_w1h[256 * K2], g_w1l[256 * K2];
__device__ __align__(256) uint32_t g_w2h[64 * K2],  g_w2l[64 * K2];
__device__ __align__(256) float g_as[NN * HEADS];
__device__ __align__(256) float g_ad[NN * HEADS];
__device__ __align__(256) float g_alpha[(size_t)EE * HEADS];
__device__ int   g_deg[NN];
__device__ int   g_cur[NN];
__device__ int   g_rowptr[NN + 1];
__device__ int   g_srcs[EE];

static inline int cdiv(int a, int b) { return (a + b - 1) / b; }

// ---------------- split helpers ----------------
// fp16 2-term split of a k-pair
__device__ __forceinline__ void split_pair_f16(float x0, float x1, uint32_t& h, uint32_t& l) {
    __half2 hh = __floats2half2_rn(x0, x1);
    float2 hf = __half22float2(hh);
    __half2 ll = __floats2half2_rn(x0 - hf.x, x1 - hf.y);
    h = *(uint32_t*)&hh;
    l = *(uint32_t*)&ll;
}

__device__ __forceinline__ void mma_f16(float c[4], uint32_t a0, uint32_t a1,
                                        uint32_t a2, uint32_t a3,
                                        uint32_t b0, uint32_t b1) {
    asm volatile(
        "mma.sync.aligned.m16n8k16.row.col.f32.f16.f16.f32 "
        "{%0,%1,%2,%3}, {%4,%5,%6,%7}, {%8,%9}, {%0,%1,%2,%3};"
        : "+f"(c[0]), "+f"(c[1]), "+f"(c[2]), "+f"(c[3])
        : "r"(a0), "r"(a1), "r"(a2), "r"(a3), "r"(b0), "r"(b1));
}

// ================= input conversion: fp32 x -> pair-packed fp16 =================
__global__ void x_to_f16(const float* __restrict__ x, uint32_t* __restrict__ x16,
                         int total) {
    for (int i = blockIdx.x * blockDim.x + threadIdx.x; i < total;
         i += gridDim.x * blockDim.x) {
        float2 v = *(const float2*)&x[(size_t)i * 2];
        __half2 hv = __floats2half2_rn(v.x, v.y);
        x16[i] = *(uint32_t*)&hv;
    }
}

// ================= W pre-split (fp16 2-term planes) =================
__global__ void split_w_f16(const float* __restrict__ W, int N, int NP,
                            uint32_t* __restrict__ wh, uint32_t* __restrict__ wl) {
    int total = NP * K2;
    for (int i = blockIdx.x * blockDim.x + threadIdx.x; i < total;
         i += gridDim.x * blockDim.x) {
        int n = i >> 7, kp = i & 127;
        uint32_t h = 0, l = 0;
        if (n < N) {
            float w0 = W[(size_t)(2 * kp) * N + n];
            float w1 = W[(size_t)(2 * kp + 1) * N + n];
            split_pair_f16(w0, w1, h, l);
        }
        wh[i] = h; wl[i] = l;
    }
}

// ================= CSR build =================
__global__ void zero_counts(int* __restrict__ deg, int* __restrict__ cur, int n) {
    for (int i = blockIdx.x * blockDim.x + threadIdx.x; i < n;
         i += gridDim.x * blockDim.x) { deg[i] = 0; cur[i] = 0; }
}
__global__ void csr_count(const int* __restrict__ dst, int E, int* __restrict__ deg) {
    for (int i = blockIdx.x * blockDim.x + threadIdx.x; i < E;
         i += gridDim.x * blockDim.x)
        atomicAdd(&deg[dst[i]], 1);
}
__global__ void csr_scan(const int* __restrict__ deg, int* __restrict__ rowptr, int n, int E) {
    __shared__ int part[1024];
    int t = threadIdx.x;
    int chunk = (n + 1023) / 1024;
    int start = t * chunk;
    int stop = min(start + chunk, n);
    int sum = 0;
    for (int i = start; i < stop; i++) sum += deg[i];
    part[t] = sum;
    __syncthreads();
    for (int o = 1; o < 1024; o <<= 1) {
        int v = (t >= o) ? part[t - o] : 0;
        __syncthreads();
        part[t] += v;
        __syncthreads();
    }
    int run = part[t] - sum;
    for (int i = start; i < stop; i++) { rowptr[i] = run; run += deg[i]; }
    if (t == 0) rowptr[n] = E;
}
__global__ void csr_fill(const int* __restrict__ src, const int* __restrict__ dst, int E,
                         const int* __restrict__ rowptr, int* __restrict__ cur,
                         int* __restrict__ srcs) {
    for (int i = blockIdx.x * blockDim.x + threadIdx.x; i < E;
         i += gridDim.x * blockDim.x) {
        int d = dst[i];
        int pos = rowptr[d] + atomicAdd(&cur[d], 1);
        srcs[pos] = src[i];
    }
}

#define PITCH 20

// ================= GEMM: fp16 A (no split) x fp16 W planes, 2-term =================
__global__ __launch_bounds__(256, 2)
void gemm_f16(const __half* __restrict__ A,
              const uint32_t* __restrict__ Bhg, const uint32_t* __restrict__ Blg,
              __half* __restrict__ C, int M, int N,
              const float* __restrict__ asrc, const float* __restrict__ adst,
              float* __restrict__ as_out, float* __restrict__ ad_out, int heads) {
    __shared__ uint32_t Ahs[128][PITCH];
    __shared__ uint32_t Bhs[64][PITCH], Bls[64][PITCH];
    __shared__ float s_as[128], s_ad[128];
    int tid = threadIdx.x;
    int lane = tid & 31;
    int warp = tid >> 5;
    int wm = warp & 3;
    int wn = warp >> 2;
    int row0 = blockIdx.y * 128;
    int col0 = blockIdx.x * 64;
    int g = lane >> 2;
    int tg = lane & 3;
    const uint32_t* A32 = (const uint32_t*)A;   // pair-packed fp16, row pitch K2

    if (tid < 128) { s_as[tid] = 0.0f; s_ad[tid] = 0.0f; }

    float acc[2][4][4];
    #pragma unroll
    for (int i = 0; i < 2; i++)
        #pragma unroll
        for (int j = 0; j < 4; j++)
            #pragma unroll
            for (int k = 0; k < 4; k++) acc[i][j][k] = 0.0f;

    int bn = tid >> 2, bc = tid & 3;

    uint4 raa[2], rbh, rbl;
    #pragma unroll
    for (int l = 0; l < 2; l++) {
        int i = tid + l * 256;
        int r = i >> 2, c4 = i & 3;
        raa[l] = make_uint4(0, 0, 0, 0);
        if (row0 + r < M)
            raa[l] = *(const uint4*)&A32[(size_t)(row0 + r) * K2 + c4 * 4];
    }
    rbh = *(const uint4*)&Bhg[(size_t)(col0 + bn) * K2 + bc * 4];
    rbl = *(const uint4*)&Blg[(size_t)(col0 + bn) * K2 + bc * 4];

    for (int kp0 = 0; kp0 < K2; kp0 += 16) {
        #pragma unroll
        for (int l = 0; l < 2; l++) {
            int i = tid + l * 256;
            int r = i >> 2, c4 = i & 3;
            *(uint4*)&Ahs[r][c4 * 4] = raa[l];
        }
        *(uint4*)&Bhs[bn][bc * 4] = rbh;
        *(uint4*)&Bls[bn][bc * 4] = rbl;
        __syncthreads();

        if (kp0 + 16 < K2) {
            #pragma unroll
            for (int l = 0; l < 2; l++) {
                int i = tid + l * 256;
                int r = i >> 2, c4 = i & 3;
                raa[l] = make_uint4(0, 0, 0, 0);
                if (row0 + r < M)
                    raa[l] = *(const uint4*)&A32[(size_t)(row0 + r) * K2 + kp0 + 16 + c4 * 4];
            }
            rbh = *(const uint4*)&Bhg[(size_t)(col0 + bn) * K2 + kp0 + 16 + bc * 4];
            rbl = *(const uint4*)&Blg[(size_t)(col0 + bn) * K2 + kp0 + 16 + bc * 4];
        }

        #pragma unroll
        for (int ks = 0; ks < 2; ks++) {
            int p0 = ks * 8 + tg, p1 = p0 + 4;
            uint32_t ah[2][4];
            #pragma unroll
            for (int mf = 0; mf < 2; mf++) {
                int rb_ = wm * 32 + mf * 16 + g;
                ah[mf][0] = Ahs[rb_][p0];  ah[mf][1] = Ahs[rb_ + 8][p0];
                ah[mf][2] = Ahs[rb_][p1];  ah[mf][3] = Ahs[rb_ + 8][p1];
            }
            uint32_t bh_[4][2], bl_[4][2];
            #pragma unroll
            for (int nf = 0; nf < 4; nf++) {
                int nb = wn * 32 + nf * 8 + g;
                bh_[nf][0] = Bhs[nb][p0];  bh_[nf][1] = Bhs[nb][p1];
                bl_[nf][0] = Bls[nb][p0];  bl_[nf][1] = Bls[nb][p1];
            }
            #pragma unroll
            for (int mf = 0; mf < 2; mf++)
                #pragma unroll
                for (int nf = 0; nf < 4; nf++) {
                    mma_f16(acc[mf][nf], ah[mf][0], ah[mf][1], ah[mf][2], ah[mf][3],
                            bl_[nf][0], bl_[nf][1]);
                    mma_f16(acc[mf][nf], ah[mf][0], ah[mf][1], ah[mf][2], ah[mf][3],
                            bh_[nf][0], bh_[nf][1]);
                }
        }
        __syncthreads();
    }

    // ---- write C (fp16) + attn partials ----
    float pa[2][2] = {}, pd[2][2] = {};
    #pragma unroll
    for (int nf = 0; nf < 4; nf++) {
        int col = col0 + wn * 32 + nf * 8 + 2 * tg;
        float av0 = 0.f, av1 = 0.f, dv0 = 0.f, dv1 = 0.f;
        if (col < N)     { av0 = asrc[col];     dv0 = adst[col]; }
        if (col + 1 < N) { av1 = asrc[col + 1]; dv1 = adst[col + 1]; }
        #pragma unroll
        for (int mf = 0; mf < 2; mf++) {
            #pragma unroll
            for (int hf_ = 0; hf_ < 2; hf_++) {
                int row = row0 + wm * 32 + mf * 16 + g + hf_ * 8;
                float c0 = acc[mf][nf][hf_ * 2], c1 = acc[mf][nf][hf_ * 2 + 1];
                if (row < M && col + 1 < N)
                    *(__half2*)&C[(size_t)row * N + col] = __floats2half2_rn(c0, c1);
                pa[mf][hf_] += c0 * av0 + c1 * av1;
                pd[mf][hf_] += c0 * dv0 + c1 * dv1;
            }
        }
    }
    #pragma unroll
    for (int o = 1; o <= 2; o <<= 1) {
        #pragma unroll
        for (int mf = 0; mf < 2; mf++)
            #pragma unroll
            for (int hf_ = 0; hf_ < 2; hf_++) {
                pa[mf][hf_] += __shfl_xor_sync(0xFFFFFFFFu, pa[mf][hf_], o);
                pd[mf][hf_] += __shfl_xor_sync(0xFFFFFFFFu, pd[mf][hf_], o);
            }
    }
    if (tg == 0) {
        #pragma unroll
        for (int mf = 0; mf < 2; mf++)
            #pragma unroll
            for (int hf_ = 0; hf_ < 2; hf_++) {
                int lr = wm * 32 + mf * 16 + g + hf_ * 8;
                atomicAdd(&s_as[lr], pa[mf][hf_]);
                atomicAdd(&s_ad[lr], pd[mf][hf_]);
            }
    }
    __syncthreads();
    if (tid < 128) {
        int row = row0 + tid;
        if (row < M) {
            int head = (heads == 1) ? 0 : (col0 >> 6);
            as_out[row * heads + head] = s_as[tid];
            ad_out[row * heads + head] = s_ad[tid];
        }
    }
}

// ---------------- fused softmax + aggregation (fp16 h), H=4 C=64, fp16 out, node range ----------------
__global__ __launch_bounds__(256)
void agg_fused4(const int* __restrict__ rowptr, const int* __restrict__ srcs,
                const float* __restrict__ as_, const float* __restrict__ ad_,
                float* __restrict__ alpha,
                const __half* __restrict__ hbuf, const float* __restrict__ bias,
                const float* __restrict__ bng, const float* __restrict__ bnb,
                const float* __restrict__ bnm, const float* __restrict__ bnv,
                __half* __restrict__ xout, int n0, int cnt) {
    __shared__ float s_al[8][32][4];
    __shared__ int   s_sr[8][32];
    int w = (blockIdx.x * blockDim.x + threadIdx.x) >> 5;
    int lane = threadIdx.x & 31;
    int wi = (threadIdx.x >> 5);
    if (w >= cnt) return;
    int d = n0 + w;
    float4 add = *(const float4*)&ad_[d * 4];
    int beg = rowptr[d], end = rowptr[d + 1];

    float d0 = 0.f, d1 = 0.f, d2 = 0.f, d3 = 0.f;
    for (int j = beg + lane; j < end; j += 32) {
        int s = srcs[j];
        float4 av = *(const float4*)&as_[s * 4];
        float e0 = av.x + add.x; e0 = (e0 > 0.f) ? e0 : NEG_SLOPE * e0;
        float e1 = av.y + add.y; e1 = (e1 > 0.f) ? e1 : NEG_SLOPE * e1;
        float e2 = av.z + add.z; e2 = (e2 > 0.f) ? e2 : NEG_SLOPE * e2;
        float e3 = av.w + add.w; e3 = (e3 > 0.f) ? e3 : NEG_SLOPE * e3;
        float p0 = __expf(e0), p1 = __expf(e1);
        float p2 = __expf(e2), p3 = __expf(e3);
        *(float4*)&alpha[(size_t)j * 4] = make_float4(p0, p1, p2, p3);
        d0 += p0; d1 += p1; d2 += p2; d3 += p3;
    }
    #pragma unroll
    for (int o = 16; o > 0; o >>= 1) {
        d0 += __shfl_xor_sync(0xFFFFFFFFu, d0, o);
        d1 += __shfl_xor_sync(0xFFFFFFFFu, d1, o);
        d2 += __shfl_xor_sync(0xFFFFFFFFu, d2, o);
        d3 += __shfl_xor_sync(0xFFFFFFFFu, d3, o);
    }
    float4 inv = make_float4(1.f / (d0 + 1e-16f), 1.f / (d1 + 1e-16f),
                             1.f / (d2 + 1e-16f), 1.f / (d3 + 1e-16f));

    int h0 = lane >> 4;
    int h1 = 2 + (lane >> 4);

    float4 acc0 = make_float4(0.f, 0.f, 0.f, 0.f);
    float4 acc1 = make_float4(0.f, 0.f, 0.f, 0.f);

    for (int jb = beg; jb < end; jb += 32) {
        int j = jb + lane;
        int s = 0;
        float4 p = make_float4(0.f, 0.f, 0.f, 0.f);
        if (j < end) {
            s = srcs[j];
            p = *(const float4*)&alpha[(size_t)j * 4];
        }
        p.x *= inv.x; p.y *= inv.y; p.z *= inv.z; p.w *= inv.w;
        __syncwarp();
        s_sr[wi][lane] = s;
        *(float4*)&s_al[wi][lane][0] = p;
        __syncwarp();
        int n = min(32, end - jb);
        #pragma unroll 4
        for (int t = 0; t < n; t++) {
            int ss = s_sr[wi][t];
            float a0 = s_al[wi][t][h0];
            float a1 = s_al[wi][t][h1];
            const uint2* hp = (const uint2*)(hbuf + (size_t)ss * FD);
            uint2 u0 = hp[lane];
            uint2 u1 = hp[32 + lane];
            float2 f00 = __half22float2(*(__half2*)&u0.x);
            float2 f01 = __half22float2(*(__half2*)&u0.y);
            float2 f10 = __half22float2(*(__half2*)&u1.x);
            float2 f11 = __half22float2(*(__half2*)&u1.y);
            acc0.x += f00.x * a0; acc0.y += f00.y * a0;
            acc0.z += f01.x * a0; acc0.w += f01.y * a0;
            acc1.x += f10.x * a1; acc1.y += f10.y * a1;
            acc1.z += f11.x * a1; acc1.w += f11.y * a1;
        }
    }

    int f0 = lane * 4, f1 = 128 + lane * 4;
    #pragma unroll
    for (int c = 0; c < 2; c++) {
        int f = c ? f1 : f0;
        float4 acc = c ? acc1 : acc0;
        float4 bv = *(const float4*)&bias[f];
        float4 gv = *(const float4*)&bng[f];
        float4 betav = *(const float4*)&bnb[f];
        float4 mv = *(const float4*)&bnm[f];
        float4 vv = *(const float4*)&bnv[f];
        float4 r;
        r.x = gv.x * (acc.x + bv.x - mv.x) * rsqrtf(vv.x + BN_EPS) + betav.x;
        r.y = gv.y * (acc.y + bv.y - mv.y) * rsqrtf(vv.y + BN_EPS) + betav.y;
        r.z = gv.z * (acc.z + bv.z - mv.z) * rsqrtf(vv.z + BN_EPS) + betav.z;
        r.w = gv.w * (acc.w + bv.w - mv.w) * rsqrtf(vv.w + BN_EPS) + betav.w;
        r.x = (r.x > 0.f) ? r.x : (expf(r.x) - 1.f);
        r.y = (r.y > 0.f) ? r.y : (expf(r.y) - 1.f);
        r.z = (r.z > 0.f) ? r.z : (expf(r.z) - 1.f);
        r.w = (r.w > 0.f) ? r.w : (expf(r.w) - 1.f);
        __half2 o0 = __floats2half2_rn(r.x, r.y);
        __half2 o1 = __floats2half2_rn(r.z, r.w);
        uint2 ov = make_uint2(*(uint32_t*)&o0, *(uint32_t*)&o1);
        *(uint2*)&xout[(size_t)d * FD + f] = ov;
    }
}

// ---------------- fused softmax + aggregation (fp16 h), H=1 C=40, node range ----------------
__global__ __launch_bounds__(256)
void agg_fused1(const int* __restrict__ rowptr, const int* __restrict__ srcs,
                const float* __restrict__ as_, const float* __restrict__ ad_,
                float* __restrict__ alpha,
                const __half* __restrict__ hbuf, const float* __restrict__ bias,
                float* __restrict__ out, int n0, int cnt) {
    __shared__ float s_al[8][32];
    __shared__ int   s_sr[8][32];
    int w = (blockIdx.x * blockDim.x + threadIdx.x) >> 5;
    int lane = threadIdx.x & 31;
    int wi = (threadIdx.x >> 5);
    if (w >= cnt) return;
    int d = n0 + w;
    float adl = ad_[d];
    int beg = rowptr[d], end = rowptr[d + 1];

    float den = 0.f;
    for (int j = beg + lane; j < end; j += 32) {
        float e = as_[srcs[j]] + adl;
        e = (e > 0.f) ? e : NEG_SLOPE * e;
        float p = __expf(e);
        alpha[j] = p;
        den += p;
    }
    #pragma unroll
    for (int o = 16; o > 0; o >>= 1)
        den += __shfl_xor_sync(0xFFFFFFFFu, den, o);
    float invden = 1.0f / (den + 1e-16f);

    float accx = 0.f, accy = 0.f;
    for (int jb = beg; jb < end; jb += 32) {
        int j = jb + lane;
        int s = 0; float p = 0.f;
        if (j < end) { s = srcs[j]; p = alpha[j]; }
        __syncwarp();
        s_sr[wi][lane] = s;
        s_al[wi][lane] = p * invden;
        __syncwarp();
        int n = min(32, end - jb);
        if (lane < OUTD / 2) {
            #pragma unroll 4
            for (int t = 0; t < n; t++) {
                int ss = s_sr[wi][t];
                float a = s_al[wi][t];
                __half2 hv = *(const __half2*)&hbuf[(size_t)ss * OUTD + 2 * lane];
                float2 f = __half22float2(hv);
                accx += f.x * a;
                accy += f.y * a;
            }
        }
    }
    if (lane < OUTD / 2) {
        out[(size_t)d * OUTD + 2 * lane]     = accx + bias[2 * lane];
        out[(size_t)d * OUTD + 2 * lane + 1] = accy + bias[2 * lane + 1];
    }
}

// ================= launch =================
extern "C" void kernel_launch(void* const* d_in, const int* in_sizes, int n_in,
                              void* d_out, int out_size) {
    const float* x       = (const float*)d_in[0];
    const int*   eidx    = (const int*)d_in[1];
    const float* W0      = (const float*)d_in[2];
    const float* a_src0  = (const float*)d_in[3];
    const float* a_dst0  = (const float*)d_in[4];
    const float* b0      = (const float*)d_in[5];
    const float* bn0_g   = (const float*)d_in[6];
    const float* bn0_b   = (const float*)d_in[7];
    const float* bn0_m   = (const float*)d_in[8];
    const float* bn0_v   = (const float*)d_in[9];
    const float* W1      = (const float*)d_in[10];
    const float* a_src1  = (const float*)d_in[11];
    const float* a_dst1  = (const float*)d_in[12];
    const float* b1      = (const float*)d_in[13];
    const float* bn1_g   = (const float*)d_in[14];
    const float* bn1_b   = (const float*)d_in[15];
    const float* bn1_m   = (const float*)d_in[16];
    const float* bn1_v   = (const float*)d_in[17];
    const float* W2      = (const float*)d_in[18];
    const float* a_src2  = (const float*)d_in[19];
    const float* a_dst2  = (const float*)d_in[20];
    const float* b2      = (const float*)d_in[21];
    float* out = (float*)d_out;

    int E = in_sizes[1] / 2;
    const int* src = eidx;
    const int* dst = eidx + E;

    float *as_buf, *ad_buf, *al_buf;
    __half *h16, *x16;
    uint32_t *w0h, *w0l, *w1h, *w1l, *w2h, *w2l;
    int *deg, *cur, *rowptr, *srcs;
    cudaGetSymbolAddress((void**)&h16, g_h16);
    cudaGetSymbolAddress((void**)&x16, g_x16);
    cudaGetSymbolAddress((void**)&w0h, g_w0h);
    cudaGetSymbolAddress((void**)&w0l, g_w0l);
    cudaGetSymbolAddress((void**)&w1h, g_w1h);
    cudaGetSymbolAddress((void**)&w1l, g_w1l);
    cudaGetSymbolAddress((void**)&w2h, g_w2h);
    cudaGetSymbolAddress((void**)&w2l, g_w2l);
    cudaGetSymbolAddress((void**)&as_buf, g_as);
    cudaGetSymbolAddress((void**)&ad_buf, g_ad);
    cudaGetSymbolAddress((void**)&al_buf, g_alpha);
    cudaGetSymbolAddress((void**)&deg, g_deg);
    cudaGetSymbolAddress((void**)&cur, g_cur);
    cudaGetSymbolAddress((void**)&rowptr, g_rowptr);
    cudaGetSymbolAddress((void**)&srcs, g_srcs);

    static cudaStream_t s2 = nullptr;
    static cudaEvent_t ev_fork = nullptr, ev_w0 = nullptr, ev_join = nullptr,
                       ev_g0 = nullptr, ev_g1A = nullptr, ev_g1B = nullptr,
                       ev_g2A = nullptr, ev_g2B = nullptr, ev_end = nullptr;
    if (s2 == nullptr) {
        cudaStreamCreateWithFlags(&s2, cudaStreamNonBlocking);
        cudaEventCreateWithFlags(&ev_fork, cudaEventDisableTiming);
        cudaEventCreateWithFlags(&ev_w0, cudaEventDisableTiming);
        cudaEventCreateWithFlags(&ev_join, cudaEventDisableTiming);
        cudaEventCreateWithFlags(&ev_g0, cudaEventDisableTiming);
        cudaEventCreateWithFlags(&ev_g1A, cudaEventDisableTiming);
        cudaEventCreateWithFlags(&ev_g1B, cudaEventDisableTiming);
        cudaEventCreateWithFlags(&ev_g2A, cudaEventDisableTiming);
        cudaEventCreateWithFlags(&ev_g2B, cudaEventDisableTiming);
        cudaEventCreateWithFlags(&ev_end, cudaEventDisableTiming);
    }

    const int HB = NN - HALF_N;

    // ---- fork: W splits + CSR build on s2 ----
    cudaEventRecord(ev_fork, 0);
    cudaStreamWaitEvent(s2, ev_fork, 0);
    split_w_f16<<<cdiv(256 * K2, 256), 256, 0, s2>>>(W0, FD, 256, w0h, w0l);
    cudaEventRecord(ev_w0, s2);
    split_w_f16<<<cdiv(256 * K2, 256), 256, 0, s2>>>(W1, FD, 256, w1h, w1l);
    split_w_f16<<<cdiv(64 * K2, 256), 256, 0, s2>>>(W2, OUTD, 64, w2h, w2l);
    zero_counts<<<cdiv(NN, 256), 256, 0, s2>>>(deg, cur, NN);
    csr_count<<<cdiv(E, 256), 256, 0, s2>>>(dst, E, deg);
    csr_scan<<<1, 1024, 0, s2>>>(deg, rowptr, NN, E);
    csr_fill<<<cdiv(E, 256), 256, 0, s2>>>(src, dst, E, rowptr, cur, srcs);
    cudaEventRecord(ev_join, s2);

    // ---- main: convert x -> fp16 (concurrent with s2 splits), then layer 0 GEMM ----
    x_to_f16<<<cdiv(NN * K2, 256), 256>>>(x, (uint32_t*)x16, NN * K2);
    cudaStreamWaitEvent(0, ev_w0, 0);
    gemm_f16<<<dim3(4, cdiv(NN, 128)), 256>>>(x16, w0h, w0l, h16, NN, FD,
                                              a_src0, a_dst0, as_buf, ad_buf, HEADS);
    cudaEventRecord(ev_g0, 0);

    // ---- agg0 split ----
    cudaStreamWaitEvent(0, ev_join, 0);
    agg_fused4<<<cdiv(HALF_N * 32, 256), 256>>>(rowptr, srcs, as_buf, ad_buf, al_buf, h16,
                                                b0, bn0_g, bn0_b, bn0_m, bn0_v, x16,
                                                0, HALF_N);
    cudaStreamWaitEvent(s2, ev_g0, 0);
    agg_fused4<<<cdiv(HB * 32, 256), 256, 0, s2>>>(rowptr, srcs, as_buf, ad_buf, al_buf, h16,
                                                   b0, bn0_g, bn0_b, bn0_m, bn0_v, x16,
                                                   HALF_N, HB);

    // ---- gemm1 split ----
    gemm_f16<<<dim3(4, cdiv(HALF_N, 128)), 256>>>(x16, w1h, w1l, h16, HALF_N, FD,
                                                  a_src1, a_dst1, as_buf, ad_buf, HEADS);
    cudaEventRecord(ev_g1A, 0);
    gemm_f16<<<dim3(4, cdiv(HB, 128)), 256, 0, s2>>>(
        x16 + (size_t)HALF_N * FD, w1h, w1l, h16 + (size_t)HALF_N * FD, HB, FD,
        a_src1, a_dst1, as_buf + HALF_N * HEADS, ad_buf + HALF_N * HEADS, HEADS);
    cudaEventRecord(ev_g1B, s2);

    // ---- agg1 split ----
    cudaStreamWaitEvent(0, ev_g1B, 0);
    agg_fused4<<<cdiv(HALF_N * 32, 256), 256>>>(rowptr, srcs, as_buf, ad_buf, al_buf, h16,
                                                b1, bn1_g, bn1_b, bn1_m, bn1_v, x16,
                                                0, HALF_N);
    cudaStreamWaitEvent(s2, ev_g1A, 0);
    agg_fused4<<<cdiv(HB * 32, 256), 256, 0, s2>>>(rowptr, srcs, as_buf, ad_buf, al_buf, h16,
                                                   b1, bn1_g, bn1_b, bn1_m, bn1_v, x16,
                                                   HALF_N, HB);

    // ---- gemm2 split ----
    gemm_f16<<<dim3(1, cdiv(HALF_N, 128)), 256>>>(x16, w2h, w2l, h16, HALF_N, OUTD,
                                                  a_src2, a_dst2, as_buf, ad_buf, 1);
    cudaEventRecord(ev_g2A, 0);
    gemm_f16<<<dim3(1, cdiv(HB, 128)), 256, 0, s2>>>(
        x16 + (size_t)HALF_N * FD, w2h, w2l, h16 + (size_t)HALF_N * OUTD, HB, OUTD,
        a_src2, a_dst2, as_buf + HALF_N, ad_buf + HALF_N, 1);
    cudaEventRecord(ev_g2B, s2);

    // ---- agg2 split ----
    cudaStreamWaitEvent(0, ev_g2B, 0);
    agg_fused1<<<cdiv(HALF_N * 32, 256), 256>>>(rowptr, srcs, as_buf, ad_buf, al_buf,
                                                h16, b2, out, 0, HALF_N);
    cudaStreamWaitEvent(s2, ev_g2A, 0);
    agg_fused1<<<cdiv(HB * 32, 256), 256, 0, s2>>>(rowptr, srcs, as_buf, ad_buf, al_buf,
                                                   h16, b2, out, HALF_N, HB);
    cudaEventRecord(ev_end, s2);
    cudaStreamWaitEvent(0, ev_end, 0);
}

// round 17
// speedup vs baseline: 1.1258x; 1.1258x over previous
#include <cuda_runtime.h>
#include <cuda_fp16.h>
#include <math.h>
#include <stdint.h>

#define NN 50000
#define EE 850000
#define FD 256      // HEADS*HID
#define HEADS 4
#define CH 64
#define OUTD 40
#define K2 128      // K/2 pairs (all GEMMs have K=256)
#define HALF_N 25088  // 196 * 128
#define BN_EPS 1e-5f
#define NEG_SLOPE 0.2f

// ---------------- scratch (static, allocation-free) ----------------
__device__ __align__(256) __half   g_h16[NN * FD];
__device__ __align__(256) __half   g_x16[NN * FD];
__device__ __align__(256) uint32_t g_w0h[256 * K2], g_w0l[256 * K2];
__device__ __align__(256) uint32_t g_w1h[256 * K2], g_w1l[256 * K2];
__device__ __align__(256) uint32_t g_w2h[64 * K2],  g_w2l[64 * K2];
__device__ __align__(256) float g_as[NN * HEADS];
__device__ __align__(256) float g_ad[NN * HEADS];
__device__ __align__(256) float g_alpha[(size_t)EE * HEADS];
__device__ int   g_deg[NN];
__device__ int   g_cur[NN];
__device__ int   g_rowptr[NN + 1];
__device__ int   g_srcs[EE];

static inline int cdiv(int a, int b) { return (a + b - 1) / b; }

// ---------------- split helpers ----------------
__device__ __forceinline__ void split_pair_f16(float x0, float x1, uint32_t& h, uint32_t& l) {
    __half2 hh = __floats2half2_rn(x0, x1);
    float2 hf = __half22float2(hh);
    __half2 ll = __floats2half2_rn(x0 - hf.x, x1 - hf.y);
    h = *(uint32_t*)&hh;
    l = *(uint32_t*)&ll;
}

__device__ __forceinline__ void mma_f16(float c[4], uint32_t a0, uint32_t a1,
                                        uint32_t a2, uint32_t a3,
                                        uint32_t b0, uint32_t b1) {
    asm volatile(
        "mma.sync.aligned.m16n8k16.row.col.f32.f16.f16.f32 "
        "{%0,%1,%2,%3}, {%4,%5,%6,%7}, {%8,%9}, {%0,%1,%2,%3};"
        : "+f"(c[0]), "+f"(c[1]), "+f"(c[2]), "+f"(c[3])
        : "r"(a0), "r"(a1), "r"(a2), "r"(a3), "r"(b0), "r"(b1));
}

// ================= input conversion: fp32 x -> pair-packed fp16 =================
__global__ void x_to_f16(const float* __restrict__ x, uint32_t* __restrict__ x16,
                         int total) {
    for (int i = blockIdx.x * blockDim.x + threadIdx.x; i < total;
         i += gridDim.x * blockDim.x) {
        float2 v = *(const float2*)&x[(size_t)i * 2];
        __half2 hv = __floats2half2_rn(v.x, v.y);
        x16[i] = *(uint32_t*)&hv;
    }
}

// ================= W pre-split (fp16 2-term planes) =================
__global__ void split_w_f16(const float* __restrict__ W, int N, int NP,
                            uint32_t* __restrict__ wh, uint32_t* __restrict__ wl) {
    int total = NP * K2;
    for (int i = blockIdx.x * blockDim.x + threadIdx.x; i < total;
         i += gridDim.x * blockDim.x) {
        int n = i >> 7, kp = i & 127;
        uint32_t h = 0, l = 0;
        if (n < N) {
            float w0 = W[(size_t)(2 * kp) * N + n];
            float w1 = W[(size_t)(2 * kp + 1) * N + n];
            split_pair_f16(w0, w1, h, l);
        }
        wh[i] = h; wl[i] = l;
    }
}

// ================= CSR build =================
__global__ void zero_counts(int* __restrict__ deg, int* __restrict__ cur, int n) {
    for (int i = blockIdx.x * blockDim.x + threadIdx.x; i < n;
         i += gridDim.x * blockDim.x) { deg[i] = 0; cur[i] = 0; }
}
__global__ void csr_count(const int* __restrict__ dst, int E, int* __restrict__ deg) {
    for (int i = blockIdx.x * blockDim.x + threadIdx.x; i < E;
         i += gridDim.x * blockDim.x)
        atomicAdd(&deg[dst[i]], 1);
}
__global__ void csr_scan(const int* __restrict__ deg, int* __restrict__ rowptr, int n, int E) {
    __shared__ int part[1024];
    int t = threadIdx.x;
    int chunk = (n + 1023) / 1024;
    int start = t * chunk;
    int stop = min(start + chunk, n);
    int sum = 0;
    for (int i = start; i < stop; i++) sum += deg[i];
    part[t] = sum;
    __syncthreads();
    for (int o = 1; o < 1024; o <<= 1) {
        int v = (t >= o) ? part[t - o] : 0;
        __syncthreads();
        part[t] += v;
        __syncthreads();
    }
    int run = part[t] - sum;
    for (int i = start; i < stop; i++) { rowptr[i] = run; run += deg[i]; }
    if (t == 0) rowptr[n] = E;
}
__global__ void csr_fill(const int* __restrict__ src, const int* __restrict__ dst, int E,
                         const int* __restrict__ rowptr, int* __restrict__ cur,
                         int* __restrict__ srcs) {
    for (int i = blockIdx.x * blockDim.x + threadIdx.x; i < E;
         i += gridDim.x * blockDim.x) {
        int d = dst[i];
        int pos = rowptr[d] + atomicAdd(&cur[d], 1);
        srcs[pos] = src[i];
    }
}

#define PITCH 20

// ================= GEMM: fp16 A (no split) x fp16 W planes, 2-term =================
__global__ __launch_bounds__(256, 2)
void gemm_f16(const __half* __restrict__ A,
              const uint32_t* __restrict__ Bhg, const uint32_t* __restrict__ Blg,
              __half* __restrict__ C, int M, int N,
              const float* __restrict__ asrc, const float* __restrict__ adst,
              float* __restrict__ as_out, float* __restrict__ ad_out, int heads) {
    __shared__ uint32_t Ahs[128][PITCH];
    __shared__ uint32_t Bhs[64][PITCH], Bls[64][PITCH];
    __shared__ float s_as[128], s_ad[128];
    int tid = threadIdx.x;
    int lane = tid & 31;
    int warp = tid >> 5;
    int wm = warp & 3;
    int wn = warp >> 2;
    int row0 = blockIdx.y * 128;
    int col0 = blockIdx.x * 64;
    int g = lane >> 2;
    int tg = lane & 3;
    const uint32_t* A32 = (const uint32_t*)A;

    if (tid < 128) { s_as[tid] = 0.0f; s_ad[tid] = 0.0f; }

    float acc[2][4][4];
    #pragma unroll
    for (int i = 0; i < 2; i++)
        #pragma unroll
        for (int j = 0; j < 4; j++)
            #pragma unroll
            for (int k = 0; k < 4; k++) acc[i][j][k] = 0.0f;

    int bn = tid >> 2, bc = tid & 3;

    uint4 raa[2], rbh, rbl;
    #pragma unroll
    for (int l = 0; l < 2; l++) {
        int i = tid + l * 256;
        int r = i >> 2, c4 = i & 3;
        raa[l] = make_uint4(0, 0, 0, 0);
        if (row0 + r < M)
            raa[l] = *(const uint4*)&A32[(size_t)(row0 + r) * K2 + c4 * 4];
    }
    rbh = *(const uint4*)&Bhg[(size_t)(col0 + bn) * K2 + bc * 4];
    rbl = *(const uint4*)&Blg[(size_t)(col0 + bn) * K2 + bc * 4];

    for (int kp0 = 0; kp0 < K2; kp0 += 16) {
        #pragma unroll
        for (int l = 0; l < 2; l++) {
            int i = tid + l * 256;
            int r = i >> 2, c4 = i & 3;
            *(uint4*)&Ahs[r][c4 * 4] = raa[l];
        }
        *(uint4*)&Bhs[bn][bc * 4] = rbh;
        *(uint4*)&Bls[bn][bc * 4] = rbl;
        __syncthreads();

        if (kp0 + 16 < K2) {
            #pragma unroll
            for (int l = 0; l < 2; l++) {
                int i = tid + l * 256;
                int r = i >> 2, c4 = i & 3;
                raa[l] = make_uint4(0, 0, 0, 0);
                if (row0 + r < M)
                    raa[l] = *(const uint4*)&A32[(size_t)(row0 + r) * K2 + kp0 + 16 + c4 * 4];
            }
            rbh = *(const uint4*)&Bhg[(size_t)(col0 + bn) * K2 + kp0 + 16 + bc * 4];
            rbl = *(const uint4*)&Blg[(size_t)(col0 + bn) * K2 + kp0 + 16 + bc * 4];
        }

        #pragma unroll
        for (int ks = 0; ks < 2; ks++) {
            int p0 = ks * 8 + tg, p1 = p0 + 4;
            uint32_t ah[2][4];
            #pragma unroll
            for (int mf = 0; mf < 2; mf++) {
                int rb_ = wm * 32 + mf * 16 + g;
                ah[mf][0] = Ahs[rb_][p0];  ah[mf][1] = Ahs[rb_ + 8][p0];
                ah[mf][2] = Ahs[rb_][p1];  ah[mf][3] = Ahs[rb_ + 8][p1];
            }
            uint32_t bh_[4][2], bl_[4][2];
            #pragma unroll
            for (int nf = 0; nf < 4; nf++) {
                int nb = wn * 32 + nf * 8 + g;
                bh_[nf][0] = Bhs[nb][p0];  bh_[nf][1] = Bhs[nb][p1];
                bl_[nf][0] = Bls[nb][p0];  bl_[nf][1] = Bls[nb][p1];
            }
            #pragma unroll
            for (int mf = 0; mf < 2; mf++)
                #pragma unroll
                for (int nf = 0; nf < 4; nf++) {
                    mma_f16(acc[mf][nf], ah[mf][0], ah[mf][1], ah[mf][2], ah[mf][3],
                            bl_[nf][0], bl_[nf][1]);
                    mma_f16(acc[mf][nf], ah[mf][0], ah[mf][1], ah[mf][2], ah[mf][3],
                            bh_[nf][0], bh_[nf][1]);
                }
        }
        __syncthreads();
    }

    // ---- write C (fp16) + attn partials ----
    float pa[2][2] = {}, pd[2][2] = {};
    #pragma unroll
    for (int nf = 0; nf < 4; nf++) {
        int col = col0 + wn * 32 + nf * 8 + 2 * tg;
        float av0 = 0.f, av1 = 0.f, dv0 = 0.f, dv1 = 0.f;
        if (col < N)     { av0 = asrc[col];     dv0 = adst[col]; }
        if (col + 1 < N) { av1 = asrc[col + 1]; dv1 = adst[col + 1]; }
        #pragma unroll
        for (int mf = 0; mf < 2; mf++) {
            #pragma unroll
            for (int hf_ = 0; hf_ < 2; hf_++) {
                int row = row0 + wm * 32 + mf * 16 + g + hf_ * 8;
                float c0 = acc[mf][nf][hf_ * 2], c1 = acc[mf][nf][hf_ * 2 + 1];
                if (row < M && col + 1 < N)
                    *(__half2*)&C[(size_t)row * N + col] = __floats2half2_rn(c0, c1);
                pa[mf][hf_] += c0 * av0 + c1 * av1;
                pd[mf][hf_] += c0 * dv0 + c1 * dv1;
            }
        }
    }
    #pragma unroll
    for (int o = 1; o <= 2; o <<= 1) {
        #pragma unroll
        for (int mf = 0; mf < 2; mf++)
            #pragma unroll
            for (int hf_ = 0; hf_ < 2; hf_++) {
                pa[mf][hf_] += __shfl_xor_sync(0xFFFFFFFFu, pa[mf][hf_], o);
                pd[mf][hf_] += __shfl_xor_sync(0xFFFFFFFFu, pd[mf][hf_], o);
            }
    }
    if (tg == 0) {
        #pragma unroll
        for (int mf = 0; mf < 2; mf++)
            #pragma unroll
            for (int hf_ = 0; hf_ < 2; hf_++) {
                int lr = wm * 32 + mf * 16 + g + hf_ * 8;
                atomicAdd(&s_as[lr], pa[mf][hf_]);
                atomicAdd(&s_ad[lr], pd[mf][hf_]);
            }
    }
    __syncthreads();
    if (tid < 128) {
        int row = row0 + tid;
        if (row < M) {
            int head = (heads == 1) ? 0 : (col0 >> 6);
            as_out[row * heads + head] = s_as[tid];
            ad_out[row * heads + head] = s_ad[tid];
        }
    }
}

// ---------------- fused softmax + aggregation (fp16 h), H=4 C=64, fp16 out, node range ----------------
__global__ __launch_bounds__(256)
void agg_fused4(const int* __restrict__ rowptr, const int* __restrict__ srcs,
                const float* __restrict__ as_, const float* __restrict__ ad_,
                float* __restrict__ alpha,
                const __half* __restrict__ hbuf, const float* __restrict__ bias,
                const float* __restrict__ bng, const float* __restrict__ bnb,
                const float* __restrict__ bnm, const float* __restrict__ bnv,
                __half* __restrict__ xout, int n0, int cnt) {
    __shared__ float s_al[8][32][4];
    __shared__ int   s_sr[8][32];
    int w = (blockIdx.x * blockDim.x + threadIdx.x) >> 5;
    int lane = threadIdx.x & 31;
    int wi = (threadIdx.x >> 5);
    if (w >= cnt) return;
    int d = n0 + w;
    float4 add = *(const float4*)&ad_[d * 4];
    int beg = rowptr[d], end = rowptr[d + 1];

    float d0 = 0.f, d1 = 0.f, d2 = 0.f, d3 = 0.f;
    for (int j = beg + lane; j < end; j += 32) {
        int s = srcs[j];
        float4 av = *(const float4*)&as_[s * 4];
        float e0 = av.x + add.x; e0 = (e0 > 0.f) ? e0 : NEG_SLOPE * e0;
        float e1 = av.y + add.y; e1 = (e1 > 0.f) ? e1 : NEG_SLOPE * e1;
        float e2 = av.z + add.z; e2 = (e2 > 0.f) ? e2 : NEG_SLOPE * e2;
        float e3 = av.w + add.w; e3 = (e3 > 0.f) ? e3 : NEG_SLOPE * e3;
        float p0 = __expf(e0), p1 = __expf(e1);
        float p2 = __expf(e2), p3 = __expf(e3);
        *(float4*)&alpha[(size_t)j * 4] = make_float4(p0, p1, p2, p3);
        d0 += p0; d1 += p1; d2 += p2; d3 += p3;
    }
    #pragma unroll
    for (int o = 16; o > 0; o >>= 1) {
        d0 += __shfl_xor_sync(0xFFFFFFFFu, d0, o);
        d1 += __shfl_xor_sync(0xFFFFFFFFu, d1, o);
        d2 += __shfl_xor_sync(0xFFFFFFFFu, d2, o);
        d3 += __shfl_xor_sync(0xFFFFFFFFu, d3, o);
    }
    float4 inv = make_float4(1.f / (d0 + 1e-16f), 1.f / (d1 + 1e-16f),
                             1.f / (d2 + 1e-16f), 1.f / (d3 + 1e-16f));

    int h0 = lane >> 4;
    int h1 = 2 + (lane >> 4);

    float4 acc0 = make_float4(0.f, 0.f, 0.f, 0.f);
    float4 acc1 = make_float4(0.f, 0.f, 0.f, 0.f);

    for (int jb = beg; jb < end; jb += 32) {
        int j = jb + lane;
        int s = 0;
        float4 p = make_float4(0.f, 0.f, 0.f, 0.f);
        if (j < end) {
            s = srcs[j];
            p = *(const float4*)&alpha[(size_t)j * 4];
        }
        p.x *= inv.x; p.y *= inv.y; p.z *= inv.z; p.w *= inv.w;
        __syncwarp();
        s_sr[wi][lane] = s;
        *(float4*)&s_al[wi][lane][0] = p;
        __syncwarp();
        int n = min(32, end - jb);
        #pragma unroll 4
        for (int t = 0; t < n; t++) {
            int ss = s_sr[wi][t];
            float a0 = s_al[wi][t][h0];
            float a1 = s_al[wi][t][h1];
            const uint2* hp = (const uint2*)(hbuf + (size_t)ss * FD);
            uint2 u0 = hp[lane];
            uint2 u1 = hp[32 + lane];
            float2 f00 = __half22float2(*(__half2*)&u0.x);
            float2 f01 = __half22float2(*(__half2*)&u0.y);
            float2 f10 = __half22float2(*(__half2*)&u1.x);
            float2 f11 = __half22float2(*(__half2*)&u1.y);
            acc0.x += f00.x * a0; acc0.y += f00.y * a0;
            acc0.z += f01.x * a0; acc0.w += f01.y * a0;
            acc1.x += f10.x * a1; acc1.y += f10.y * a1;
            acc1.z += f11.x * a1; acc1.w += f11.y * a1;
        }
    }

    int f0 = lane * 4, f1 = 128 + lane * 4;
    #pragma unroll
    for (int c = 0; c < 2; c++) {
        int f = c ? f1 : f0;
        float4 acc = c ? acc1 : acc0;
        float4 bv = *(const float4*)&bias[f];
        float4 gv = *(const float4*)&bng[f];
        float4 betav = *(const float4*)&bnb[f];
        float4 mv = *(const float4*)&bnm[f];
        float4 vv = *(const float4*)&bnv[f];
        float4 r;
        r.x = gv.x * (acc.x + bv.x - mv.x) * rsqrtf(vv.x + BN_EPS) + betav.x;
        r.y = gv.y * (acc.y + bv.y - mv.y) * rsqrtf(vv.y + BN_EPS) + betav.y;
        r.z = gv.z * (acc.z + bv.z - mv.z) * rsqrtf(vv.z + BN_EPS) + betav.z;
        r.w = gv.w * (acc.w + bv.w - mv.w) * rsqrtf(vv.w + BN_EPS) + betav.w;
        r.x = (r.x > 0.f) ? r.x : (expf(r.x) - 1.f);
        r.y = (r.y > 0.f) ? r.y : (expf(r.y) - 1.f);
        r.z = (r.z > 0.f) ? r.z : (expf(r.z) - 1.f);
        r.w = (r.w > 0.f) ? r.w : (expf(r.w) - 1.f);
        __half2 o0 = __floats2half2_rn(r.x, r.y);
        __half2 o1 = __floats2half2_rn(r.z, r.w);
        uint2 ov = make_uint2(*(uint32_t*)&o0, *(uint32_t*)&o1);
        *(uint2*)&xout[(size_t)d * FD + f] = ov;
    }
}

// ---------------- fused softmax + aggregation (fp16 h), H=1 C=40, node range ----------------
__global__ __launch_bounds__(256)
void agg_fused1(const int* __restrict__ rowptr, const int* __restrict__ srcs,
                const float* __restrict__ as_, const float* __restrict__ ad_,
                float* __restrict__ alpha,
                const __half* __restrict__ hbuf, const float* __restrict__ bias,
                float* __restrict__ out, int n0, int cnt) {
    __shared__ float s_al[8][32];
    __shared__ int   s_sr[8][32];
    int w = (blockIdx.x * blockDim.x + threadIdx.x) >> 5;
    int lane = threadIdx.x & 31;
    int wi = (threadIdx.x >> 5);
    if (w >= cnt) return;
    int d = n0 + w;
    float adl = ad_[d];
    int beg = rowptr[d], end = rowptr[d + 1];

    float den = 0.f;
    for (int j = beg + lane; j < end; j += 32) {
        float e = as_[srcs[j]] + adl;
        e = (e > 0.f) ? e : NEG_SLOPE * e;
        float p = __expf(e);
        alpha[j] = p;
        den += p;
    }
    #pragma unroll
    for (int o = 16; o > 0; o >>= 1)
        den += __shfl_xor_sync(0xFFFFFFFFu, den, o);
    float invden = 1.0f / (den + 1e-16f);

    float accx = 0.f, accy = 0.f;
    for (int jb = beg; jb < end; jb += 32) {
        int j = jb + lane;
        int s = 0; float p = 0.f;
        if (j < end) { s = srcs[j]; p = alpha[j]; }
        __syncwarp();
        s_sr[wi][lane] = s;
        s_al[wi][lane] = p * invden;
        __syncwarp();
        int n = min(32, end - jb);
        if (lane < OUTD / 2) {
            #pragma unroll 4
            for (int t = 0; t < n; t++) {
                int ss = s_sr[wi][t];
                float a = s_al[wi][t];
                __half2 hv = *(const __half2*)&hbuf[(size_t)ss * OUTD + 2 * lane];
                float2 f = __half22float2(hv);
                accx += f.x * a;
                accy += f.y * a;
            }
        }
    }
    if (lane < OUTD / 2) {
        out[(size_t)d * OUTD + 2 * lane]     = accx + bias[2 * lane];
        out[(size_t)d * OUTD + 2 * lane + 1] = accy + bias[2 * lane + 1];
    }
}

// ================= launch =================
extern "C" void kernel_launch(void* const* d_in, const int* in_sizes, int n_in,
                              void* d_out, int out_size) {
    const float* x       = (const float*)d_in[0];
    const int*   eidx    = (const int*)d_in[1];
    const float* W0      = (const float*)d_in[2];
    const float* a_src0  = (const float*)d_in[3];
    const float* a_dst0  = (const float*)d_in[4];
    const float* b0      = (const float*)d_in[5];
    const float* bn0_g   = (const float*)d_in[6];
    const float* bn0_b   = (const float*)d_in[7];
    const float* bn0_m   = (const float*)d_in[8];
    const float* bn0_v   = (const float*)d_in[9];
    const float* W1      = (const float*)d_in[10];
    const float* a_src1  = (const float*)d_in[11];
    const float* a_dst1  = (const float*)d_in[12];
    const float* b1      = (const float*)d_in[13];
    const float* bn1_g   = (const float*)d_in[14];
    const float* bn1_b   = (const float*)d_in[15];
    const float* bn1_m   = (const float*)d_in[16];
    const float* bn1_v   = (const float*)d_in[17];
    const float* W2      = (const float*)d_in[18];
    const float* a_src2  = (const float*)d_in[19];
    const float* a_dst2  = (const float*)d_in[20];
    const float* b2      = (const float*)d_in[21];
    float* out = (float*)d_out;

    int E = in_sizes[1] / 2;
    const int* src = eidx;
    const int* dst = eidx + E;

    float *as_buf, *ad_buf, *al_buf;
    __half *h16, *x16;
    uint32_t *w0h, *w0l, *w1h, *w1l, *w2h, *w2l;
    int *deg, *cur, *rowptr, *srcs;
    cudaGetSymbolAddress((void**)&h16, g_h16);
    cudaGetSymbolAddress((void**)&x16, g_x16);
    cudaGetSymbolAddress((void**)&w0h, g_w0h);
    cudaGetSymbolAddress((void**)&w0l, g_w0l);
    cudaGetSymbolAddress((void**)&w1h, g_w1h);
    cudaGetSymbolAddress((void**)&w1l, g_w1l);
    cudaGetSymbolAddress((void**)&w2h, g_w2h);
    cudaGetSymbolAddress((void**)&w2l, g_w2l);
    cudaGetSymbolAddress((void**)&as_buf, g_as);
    cudaGetSymbolAddress((void**)&ad_buf, g_ad);
    cudaGetSymbolAddress((void**)&al_buf, g_alpha);
    cudaGetSymbolAddress((void**)&deg, g_deg);
    cudaGetSymbolAddress((void**)&cur, g_cur);
    cudaGetSymbolAddress((void**)&rowptr, g_rowptr);
    cudaGetSymbolAddress((void**)&srcs, g_srcs);

    static cudaStream_t s2 = nullptr, s3 = nullptr;
    static cudaEvent_t ev_fork = nullptr, ev_w0 = nullptr, ev_w12 = nullptr,
                       ev_join = nullptr, ev_g0A = nullptr, ev_g0B = nullptr,
                       ev_g1A = nullptr, ev_g1B = nullptr,
                       ev_g2A = nullptr, ev_g2B = nullptr, ev_end = nullptr;
    if (s2 == nullptr) {
        cudaStreamCreateWithFlags(&s2, cudaStreamNonBlocking);
        cudaStreamCreateWithFlags(&s3, cudaStreamNonBlocking);
        cudaEventCreateWithFlags(&ev_fork, cudaEventDisableTiming);
        cudaEventCreateWithFlags(&ev_w0, cudaEventDisableTiming);
        cudaEventCreateWithFlags(&ev_w12, cudaEventDisableTiming);
        cudaEventCreateWithFlags(&ev_join, cudaEventDisableTiming);
        cudaEventCreateWithFlags(&ev_g0A, cudaEventDisableTiming);
        cudaEventCreateWithFlags(&ev_g0B, cudaEventDisableTiming);
        cudaEventCreateWithFlags(&ev_g1A, cudaEventDisableTiming);
        cudaEventCreateWithFlags(&ev_g1B, cudaEventDisableTiming);
        cudaEventCreateWithFlags(&ev_g2A, cudaEventDisableTiming);
        cudaEventCreateWithFlags(&ev_g2B, cudaEventDisableTiming);
        cudaEventCreateWithFlags(&ev_end, cudaEventDisableTiming);
    }

    const int HB = NN - HALF_N;

    // ---- fork ----
    cudaEventRecord(ev_fork, 0);
    cudaStreamWaitEvent(s2, ev_fork, 0);
    cudaStreamWaitEvent(s3, ev_fork, 0);

    // s3: CSR chain, then W1/W2 splits
    zero_counts<<<cdiv(NN, 256), 256, 0, s3>>>(deg, cur, NN);
    csr_count<<<cdiv(E, 256), 256, 0, s3>>>(dst, E, deg);
    csr_scan<<<1, 1024, 0, s3>>>(deg, rowptr, NN, E);
    csr_fill<<<cdiv(E, 256), 256, 0, s3>>>(src, dst, E, rowptr, cur, srcs);
    cudaEventRecord(ev_join, s3);
    split_w_f16<<<cdiv(256 * K2, 256), 256, 0, s3>>>(W1, FD, 256, w1h, w1l);
    split_w_f16<<<cdiv(64 * K2, 256), 256, 0, s3>>>(W2, OUTD, 64, w2h, w2l);
    cudaEventRecord(ev_w12, s3);

    // s2: W0 split, convert x half B, gemm0 half B
    split_w_f16<<<cdiv(256 * K2, 256), 256, 0, s2>>>(W0, FD, 256, w0h, w0l);
    cudaEventRecord(ev_w0, s2);
    x_to_f16<<<cdiv(HB * K2, 256), 256, 0, s2>>>(x + (size_t)HALF_N * FD,
                                                 (uint32_t*)x16 + (size_t)HALF_N * K2,
                                                 HB * K2);
    gemm_f16<<<dim3(4, cdiv(HB, 128)), 256, 0, s2>>>(
        x16 + (size_t)HALF_N * FD, w0h, w0l, h16 + (size_t)HALF_N * FD, HB, FD,
        a_src0, a_dst0, as_buf + HALF_N * HEADS, ad_buf + HALF_N * HEADS, HEADS);
    cudaEventRecord(ev_g0B, s2);

    // main: convert x half A, gemm0 half A
    x_to_f16<<<cdiv(HALF_N * K2, 256), 256>>>(x, (uint32_t*)x16, HALF_N * K2);
    cudaStreamWaitEvent(0, ev_w0, 0);
    gemm_f16<<<dim3(4, cdiv(HALF_N, 128)), 256>>>(x16, w0h, w0l, h16, HALF_N, FD,
                                                  a_src0, a_dst0, as_buf, ad_buf, HEADS);
    cudaEventRecord(ev_g0A, 0);

    // ---- agg0 split (needs both gemm0 halves + CSR) ----
    cudaStreamWaitEvent(0, ev_join, 0);
    cudaStreamWaitEvent(0, ev_g0B, 0);
    agg_fused4<<<cdiv(HALF_N * 32, 256), 256>>>(rowptr, srcs, as_buf, ad_buf, al_buf, h16,
                                                b0, bn0_g, bn0_b, bn0_m, bn0_v, x16,
                                                0, HALF_N);
    cudaStreamWaitEvent(s2, ev_join, 0);
    cudaStreamWaitEvent(s2, ev_g0A, 0);
    agg_fused4<<<cdiv(HB * 32, 256), 256, 0, s2>>>(rowptr, srcs, as_buf, ad_buf, al_buf, h16,
                                                   b0, bn0_g, bn0_b, bn0_m, bn0_v, x16,
                                                   HALF_N, HB);

    // ---- gemm1 split (needs W1 from s3) ----
    cudaStreamWaitEvent(0, ev_w12, 0);
    gemm_f16<<<dim3(4, cdiv(HALF_N, 128)), 256>>>(x16, w1h, w1l, h16, HALF_N, FD,
                                                  a_src1, a_dst1, as_buf, ad_buf, HEADS);
    cudaEventRecord(ev_g1A, 0);
    cudaStreamWaitEvent(s2, ev_w12, 0);
    gemm_f16<<<dim3(4, cdiv(HB, 128)), 256, 0, s2>>>(
        x16 + (size_t)HALF_N * FD, w1h, w1l, h16 + (size_t)HALF_N * FD, HB, FD,
        a_src1, a_dst1, as_buf + HALF_N * HEADS, ad_buf + HALF_N * HEADS, HEADS);
    cudaEventRecord(ev_g1B, s2);

    // ---- agg1 split ----
    cudaStreamWaitEvent(0, ev_g1B, 0);
    agg_fused4<<<cdiv(HALF_N * 32, 256), 256>>>(rowptr, srcs, as_buf, ad_buf, al_buf, h16,
                                                b1, bn1_g, bn1_b, bn1_m, bn1_v, x16,
                                                0, HALF_N);
    cudaStreamWaitEvent(s2, ev_g1A, 0);
    agg_fused4<<<cdiv(HB * 32, 256), 256, 0, s2>>>(rowptr, srcs, as_buf, ad_buf, al_buf, h16,
                                                   b1, bn1_g, bn1_b, bn1_m, bn1_v, x16,
                                                   HALF_N, HB);

    // ---- gemm2 split ----
    gemm_f16<<<dim3(1, cdiv(HALF_N, 128)), 256>>>(x16, w2h, w2l, h16, HALF_N, OUTD,
                                                  a_src2, a_dst2, as_buf, ad_buf, 1);
    cudaEventRecord(ev_g2A, 0);
    gemm_f16<<<dim3(1, cdiv(HB, 128)), 256, 0, s2>>>(
        x16 + (size_t)HALF_N * FD, w2h, w2l, h16 + (size_t)HALF_N * OUTD, HB, OUTD,
        a_src2, a_dst2, as_buf + HALF_N, ad_buf + HALF_N, 1);
    cudaEventRecord(ev_g2B, s2);

    // ---- agg2 split ----
    cudaStreamWaitEvent(0, ev_g2B, 0);
    agg_fused1<<<cdiv(HALF_N * 32, 256), 256>>>(rowptr, srcs, as_buf, ad_buf, al_buf,
                                                h16, b2, out, 0, HALF_N);
    cudaStreamWaitEvent(s2, ev_g2A, 0);
    agg_fused1<<<cdiv(HB * 32, 256), 256, 0, s2>>>(rowptr, srcs, as_buf, ad_buf, al_buf,
                                                   h16, b2, out, HALF_N, HB);
    cudaEventRecord(ev_end, s2);
    cudaStreamWaitEvent(0, ev_end, 0);
}